// round 1
// baseline (speedup 1.0000x reference)
#include <cuda_runtime.h>
#include <math.h>

// NTXentLoss: zis [4096,256], zjs [4096,256] fp32 -> scalar fp32 loss.
// reps = concat(zjs, zis) [8192, 256]; z = reps / max(||reps||, 1e-8)
// sim = z @ z^T ; pos_i = sim[i, (i+4096)%8192]/T ; lse over row excluding diag
// loss = mean(lse - pos), T = 0.5

#define M_TOTAL 8192
#define N_HALF  4096
#define DDIM    256
#define INV_T   2.0f            // 1 / 0.5
#define BT      64              // GEMM tile (rows == cols)

// Scratch (allocation-free rule: __device__ globals)
__device__ float g_zT[DDIM * M_TOTAL];   // normalized, k-major: zT[k][i], 8 MB
__device__ float g_pos[M_TOTAL];         // sim[i, pair]/T
__device__ float g_s[M_TOTAL];           // sum_{j != i} exp(sim_ij / T)

// ---------------------------------------------------------------------------
// Kernel A: normalize rows of reps and store transposed (k-major).
// 256 blocks x 256 threads, 32 rows per block.
// ---------------------------------------------------------------------------
__global__ __launch_bounds__(256) void norm_transpose_kernel(
    const float* __restrict__ zis, const float* __restrict__ zjs)
{
    __shared__ float tile[32][DDIM + 1];   // +1 pad: conflict-free transposed read
    __shared__ float inv_norm[32];

    const int tid = threadIdx.x;
    const int rowbase = blockIdx.x * 32;

    // Coalesced load of 32 rows (8192 floats)
    #pragma unroll
    for (int it = 0; it < 32; ++it) {
        int idx = it * 256 + tid;
        int r = idx >> 8;           // /256
        int k = idx & 255;
        int grow = rowbase + r;
        float v = (grow < N_HALF) ? zjs[grow * DDIM + k]
                                  : zis[(grow - N_HALF) * DDIM + k];
        tile[r][k] = v;
    }
    __syncthreads();

    // Per-row sum of squares: 8 warps, 4 rows each
    const int wid = tid >> 5, lane = tid & 31;
    for (int rr = wid; rr < 32; rr += 8) {
        float ss = 0.0f;
        #pragma unroll
        for (int k = lane; k < DDIM; k += 32) {
            float v = tile[rr][k];
            ss += v * v;
        }
        #pragma unroll
        for (int o = 16; o > 0; o >>= 1)
            ss += __shfl_xor_sync(0xffffffffu, ss, o);
        if (lane == 0)
            inv_norm[rr] = 1.0f / fmaxf(sqrtf(ss), 1e-8f);
    }
    __syncthreads();

    // Store transposed, normalized: g_zT[k][rowbase+rr], coalesced per warp
    const int rr = tid & 31;
    const int k0 = tid >> 5;
    const float inv = inv_norm[rr];
    #pragma unroll
    for (int it = 0; it < 32; ++it) {
        int k = it * 8 + k0;
        g_zT[k * M_TOTAL + rowbase + rr] = tile[rr][k] * inv;
    }
}

// ---------------------------------------------------------------------------
// Kernel C: positive-pair dots. pos_i = pos_{i+N} = dot(z_i, z_{i+N}) * INV_T.
// 16 blocks x 256 threads, one i per thread.
// ---------------------------------------------------------------------------
__global__ __launch_bounds__(256) void pos_kernel()
{
    const int i = blockIdx.x * 256 + threadIdx.x;   // 0..4095
    float a0 = 0.f, a1 = 0.f, a2 = 0.f, a3 = 0.f;
    #pragma unroll 8
    for (int k = 0; k < DDIM; k += 4) {
        a0 += g_zT[(k + 0) * M_TOTAL + i] * g_zT[(k + 0) * M_TOTAL + i + N_HALF];
        a1 += g_zT[(k + 1) * M_TOTAL + i] * g_zT[(k + 1) * M_TOTAL + i + N_HALF];
        a2 += g_zT[(k + 2) * M_TOTAL + i] * g_zT[(k + 2) * M_TOTAL + i + N_HALF];
        a3 += g_zT[(k + 3) * M_TOTAL + i] * g_zT[(k + 3) * M_TOTAL + i + N_HALF];
    }
    float p = (a0 + a1 + a2 + a3) * INV_T;
    g_pos[i] = p;
    g_pos[i + N_HALF] = p;
}

// ---------------------------------------------------------------------------
// Kernel B: tiled sim GEMM fused with exp-sum epilogue (diag masked).
// 128 blocks (64 rows each) x 256 threads (16x16), 4x4 micro-tile per thread.
// Shared: As[k][r] 64KB resident + Bs[k][c] 64KB streamed per column tile.
// No running max needed: sim/T in [-2, 2] -> sum(exp) < 8191 * e^2, fp32-safe.
// ---------------------------------------------------------------------------
__global__ __launch_bounds__(256) void simloss_kernel()
{
    extern __shared__ float sm[];
    float* As = sm;                    // [256][64]
    float* Bs = sm + DDIM * BT;        // [256][64]

    const int tid = threadIdx.x;
    const int tx = tid & 15;           // column group
    const int ty = tid >> 4;           // row group
    const int rbase = blockIdx.x * BT;
    const int r0 = rbase + ty * 4;

    // Load A tile once: As[k][j] = zT[k][rbase + j]  (coalesced, conflict-free)
    #pragma unroll
    for (int it = 0; it < 16; ++it) {
        int idx = it * 256 + tid;
        int k = idx >> 4;
        int j = idx & 15;
        *reinterpret_cast<float4*>(&As[k * BT + 4 * j]) =
            *reinterpret_cast<const float4*>(&g_zT[k * M_TOTAL + rbase + 4 * j]);
    }

    float s[4] = {0.f, 0.f, 0.f, 0.f};

    for (int jt = 0; jt < M_TOTAL / BT; ++jt) {
        const int cbase = jt * BT;
        __syncthreads();   // previous tile fully consumed before overwriting Bs
        #pragma unroll
        for (int it = 0; it < 16; ++it) {
            int idx = it * 256 + tid;
            int k = idx >> 4;
            int j = idx & 15;
            *reinterpret_cast<float4*>(&Bs[k * BT + 4 * j]) =
                *reinterpret_cast<const float4*>(&g_zT[k * M_TOTAL + cbase + 4 * j]);
        }
        __syncthreads();

        float acc[4][4] = {};
        #pragma unroll 8
        for (int k = 0; k < DDIM; ++k) {
            float4 a = *reinterpret_cast<const float4*>(&As[k * BT + ty * 4]);
            float4 b = *reinterpret_cast<const float4*>(&Bs[k * BT + tx * 4]);
            float ar[4] = {a.x, a.y, a.z, a.w};
            float br[4] = {b.x, b.y, b.z, b.w};
            #pragma unroll
            for (int i = 0; i < 4; ++i)
                #pragma unroll
                for (int j = 0; j < 4; ++j)
                    acc[i][j] = fmaf(ar[i], br[j], acc[i][j]);
        }

        // Fused epilogue: s_i += exp(sim/T), skipping the diagonal
        const int c0 = cbase + tx * 4;
        #pragma unroll
        for (int i = 0; i < 4; ++i) {
            #pragma unroll
            for (int j = 0; j < 4; ++j) {
                float e = __expf(acc[i][j] * INV_T);
                if (r0 + i == c0 + j) e = 0.0f;   // mask diagonal
                s[i] += e;
            }
        }
    }

    // Cross-thread reduce: 16 tx-partials per row. Reuse As region as scratch.
    __syncthreads();
    float* red = sm;   // [64][17]
    #pragma unroll
    for (int i = 0; i < 4; ++i)
        red[(ty * 4 + i) * 17 + tx] = s[i];
    __syncthreads();
    if (tid < 64) {
        float t = 0.f;
        #pragma unroll
        for (int x = 0; x < 16; ++x)
            t += red[tid * 17 + x];
        g_s[rbase + tid] = t;
    }
}

// ---------------------------------------------------------------------------
// Kernel D: loss = mean(log(g_s) - g_pos)
// ---------------------------------------------------------------------------
__global__ __launch_bounds__(256) void reduce_kernel(float* __restrict__ out)
{
    __shared__ float red[8];
    const int tid = threadIdx.x;
    float acc = 0.f;
    for (int i = tid; i < M_TOTAL; i += 256)
        acc += logf(g_s[i]) - g_pos[i];
    #pragma unroll
    for (int o = 16; o > 0; o >>= 1)
        acc += __shfl_xor_sync(0xffffffffu, acc, o);
    if ((tid & 31) == 0) red[tid >> 5] = acc;
    __syncthreads();
    if (tid == 0) {
        float t = 0.f;
        #pragma unroll
        for (int w = 0; w < 8; ++w) t += red[w];
        out[0] = t / (float)M_TOTAL;
    }
}

// ---------------------------------------------------------------------------
extern "C" void kernel_launch(void* const* d_in, const int* in_sizes, int n_in,
                              void* d_out, int out_size)
{
    const float* zis = (const float*)d_in[0];
    const float* zjs = (const float*)d_in[1];
    float* out = (float*)d_out;

    norm_transpose_kernel<<<M_TOTAL / 32, 256>>>(zis, zjs);
    pos_kernel<<<N_HALF / 256, 256>>>();

    const int smem_b = 2 * DDIM * BT * (int)sizeof(float);   // 128 KB
    cudaFuncSetAttribute(simloss_kernel,
                         cudaFuncAttributeMaxDynamicSharedMemorySize, smem_b);
    simloss_kernel<<<M_TOTAL / BT, 256, smem_b>>>();

    reduce_kernel<<<1, 256>>>(out);
}

// round 5
// speedup vs baseline: 10.8764x; 10.8764x over previous
#include <cuda_runtime.h>
#include <cuda_bf16.h>
#include <cstdint>
#include <math.h>

// NTXentLoss via mma.sync (HMMA) bf16 GEMM with fused exp-sum epilogue.
// (tcgen05 is unavailable: harness compiles through compute_103 virtual arch.)
// reps = concat(zjs, zis) [8192,256]; Z = normalize(reps) -> bf16.
// sim = Z @ Z^T ; loss = mean_i [ log(sum_{j!=i} exp(2*sim_ij)) - 2*sim_{i,pair} ]

#define M_TOTAL 8192
#define N_HALF  4096
#define DDIM    256
#define RT      128            // CTA row tile
#define CT      128            // CTA col tile
#define CSPLIT  2
#define COLS_PER_CTA (M_TOTAL / CSPLIT)
#define NTILES  (COLS_PER_CTA / CT)      // 32
#define SMS     (DDIM + 8)               // smem row stride in bf16 (pad: no bank conflicts)
#define SMS_B   (SMS * 2)                // ... in bytes (528)

// Scratch (__device__ globals: allocation-free rule)
__device__ __nv_bfloat16 g_Z[M_TOTAL * DDIM];     // normalized bf16, row-major
__device__ float g_pos[M_TOTAL];                  // 2*sim[i, pair]
__device__ float g_spart[CSPLIT * M_TOTAL];       // partial exp-sums per col-split

// smem layout (bytes)
#define SM_A   0
#define SM_B0  (RT * SMS_B)              // 67584
#define SM_B1  (SM_B0 * 2)               // 135168
#define SMEM_BYTES (SM_B0 * 3)           // 202752

// ---------------- PTX helpers (compute_103-safe subset) ----------------
__device__ __forceinline__ uint32_t smem_to_u32(const void* p) {
    uint32_t a;
    asm("{ .reg .u64 t; cvta.to.shared.u64 t, %1; cvt.u32.u64 %0, t; }"
        : "=r"(a) : "l"(p));
    return a;
}
__device__ __forceinline__ void ldsm4(uint32_t* r, uint32_t addr) {
    asm volatile("ldmatrix.sync.aligned.m8n8.x4.shared.b16 {%0,%1,%2,%3}, [%4];"
                 : "=r"(r[0]), "=r"(r[1]), "=r"(r[2]), "=r"(r[3]) : "r"(addr));
}
__device__ __forceinline__ void mma16816(float* d, const uint32_t* a, const uint32_t* b) {
    asm volatile(
        "mma.sync.aligned.m16n8k16.row.col.f32.bf16.bf16.f32 "
        "{%0,%1,%2,%3}, {%4,%5,%6,%7}, {%8,%9}, {%0,%1,%2,%3};"
        : "+f"(d[0]), "+f"(d[1]), "+f"(d[2]), "+f"(d[3])
        : "r"(a[0]), "r"(a[1]), "r"(a[2]), "r"(a[3]), "r"(b[0]), "r"(b[1]));
}
__device__ __forceinline__ void cp16(uint32_t smaddr, const void* gptr) {
    asm volatile("cp.async.cg.shared.global [%0], [%1], 16;"
                 :: "r"(smaddr), "l"(gptr) : "memory");
}
#define CP_COMMIT() asm volatile("cp.async.commit_group;" ::: "memory")
template <int N>
__device__ __forceinline__ void cp_wait() {
    asm volatile("cp.async.wait_group %0;" :: "n"(N) : "memory");
}

// Async-copy one 128x256 bf16 tile (g_Z rows row0..row0+127) into smem
// at byte offset sm_off, padded row stride SMS_B. 256 threads, 16 chunks each.
__device__ __forceinline__ void cp_tile(uint32_t smem_base, int sm_off, int row0) {
    const int tid = threadIdx.x;
    #pragma unroll
    for (int it = 0; it < 16; ++it) {
        int idx = it * 256 + tid;            // 4096 16B chunks
        int r = idx >> 5;
        int c = idx & 31;                    // 16B chunk within row
        cp16(smem_base + sm_off + r * SMS_B + c * 16,
             g_Z + (size_t)(row0 + r) * DDIM + c * 8);
    }
}

// ---------------------------------------------------------------------------
// Kernel A: normalize + bf16 quantize. One warp per row.
// ---------------------------------------------------------------------------
__global__ __launch_bounds__(256) void norm_kernel(const float* __restrict__ zis,
                                                   const float* __restrict__ zjs)
{
    const int wid = threadIdx.x >> 5, lane = threadIdx.x & 31;
    const int r = blockIdx.x * 8 + wid;
    const float* src = (r < N_HALF) ? (zjs + (size_t)r * DDIM)
                                    : (zis + (size_t)(r - N_HALF) * DDIM);
    float4 v0 = reinterpret_cast<const float4*>(src)[lane];
    float4 v1 = reinterpret_cast<const float4*>(src)[lane + 32];
    float ss = v0.x*v0.x + v0.y*v0.y + v0.z*v0.z + v0.w*v0.w
             + v1.x*v1.x + v1.y*v1.y + v1.z*v1.z + v1.w*v1.w;
    #pragma unroll
    for (int o = 16; o > 0; o >>= 1) ss += __shfl_xor_sync(0xffffffffu, ss, o);
    float inv = 1.0f / fmaxf(sqrtf(ss), 1e-8f);
    __nv_bfloat162* dst = reinterpret_cast<__nv_bfloat162*>(g_Z + (size_t)r * DDIM);
    dst[lane * 2 + 0]      = __floats2bfloat162_rn(v0.x * inv, v0.y * inv);
    dst[lane * 2 + 1]      = __floats2bfloat162_rn(v0.z * inv, v0.w * inv);
    dst[64 + lane * 2 + 0] = __floats2bfloat162_rn(v1.x * inv, v1.y * inv);
    dst[64 + lane * 2 + 1] = __floats2bfloat162_rn(v1.z * inv, v1.w * inv);
}

// ---------------------------------------------------------------------------
// Kernel C: positive-pair dots (bf16, consistent with sim). One warp per pair.
// ---------------------------------------------------------------------------
__global__ __launch_bounds__(256) void pos_kernel()
{
    const int wid = threadIdx.x >> 5, lane = threadIdx.x & 31;
    const int i = blockIdx.x * 8 + wid;
    const __nv_bfloat162* a = reinterpret_cast<const __nv_bfloat162*>(g_Z + (size_t)i * DDIM);
    const __nv_bfloat162* b = reinterpret_cast<const __nv_bfloat162*>(g_Z + (size_t)(i + N_HALF) * DDIM);
    float acc = 0.f;
    #pragma unroll
    for (int q = 0; q < 4; ++q) {
        float2 fa = __bfloat1622float2(a[lane + 32 * q]);
        float2 fb = __bfloat1622float2(b[lane + 32 * q]);
        acc = fmaf(fa.x, fb.x, acc);
        acc = fmaf(fa.y, fb.y, acc);
    }
    #pragma unroll
    for (int o = 16; o > 0; o >>= 1) acc += __shfl_xor_sync(0xffffffffu, acc, o);
    if (lane == 0) {
        g_pos[i] = 2.0f * acc;
        g_pos[i + N_HALF] = 2.0f * acc;
    }
}

// ---------------------------------------------------------------------------
// Kernel B: HMMA bf16 GEMM + fused exp-sum epilogue.
// grid (64, 2): x = row tile (128 rows), y = col split (4096 cols).
// 256 threads = 8 warps in 2(M) x 4(N); warp tile 64x32.
// A resident in smem; B double-buffered via cp.async. Accums in registers.
// No running max needed: sim/T in [-4,4] after bf16 error -> fp32 sum safe.
// ---------------------------------------------------------------------------
__global__ __launch_bounds__(256) void simexp_kernel()
{
    extern __shared__ char sm[];
    const uint32_t smb = smem_to_u32(sm);
    const int tid = threadIdx.x;
    const int wid = tid >> 5;
    const int lane = tid & 31;
    const int wm = wid >> 2;              // 0..1 (M)
    const int wn = wid & 3;               // 0..3 (N)
    const int rb = blockIdx.x * RT;
    const int cs = blockIdx.y;
    const int gcb0 = cs * COLS_PER_CTA;

    // Per-thread ldmatrix address components (frag f of x4 = reg f):
    //  A x4: f0=rows0-7/k0-7, f1=rows8-15/k0-7, f2=rows0-7/k8-15, f3=rows8-15/k8-15
    //    lanes 0-7: rows+0,k0 | 8-15: rows+8,k0 | 16-23: rows+0,k8 | 24-31: rows+8,k8
    //  B x4: f0=n0-7/k0-7,    f1=n0-7/k8-15,    f2=n8-15/k0-7,    f3=n8-15/k8-15
    //    lanes 0-7: n+0,k0   | 8-15: n+0,k8    | 16-23: n+8,k0   | 24-31: n+8,k8
    const int a_row = wm * 64 + (lane & 7) + ((lane >> 3) & 1) * 8;
    const int a_kad = (lane >> 4) * 8;                       // k add (elements)
    const int b_row = wn * 32 + (lane & 7) + ((lane >> 4) & 1) * 8;   // FIXED: *8 not *16
    const int b_kad = ((lane >> 3) & 1) * 8;

    // Prologue: async load A tile + first B tile (one commit group)
    cp_tile(smb, SM_A, rb);
    cp_tile(smb, SM_B0, gcb0);
    CP_COMMIT();

    float rsum[8];                         // [mf*2 + rowhalf]
    #pragma unroll
    for (int s = 0; s < 8; ++s) rsum[s] = 0.f;

    const int drow0 = rb + wm * 64 + (lane >> 2);      // global row of d0/d1
    const int dcol0 = 2 * (lane & 3);                  // col offset within n8

    for (int t = 0; t < NTILES; ++t) {
        __syncthreads();                   // everyone done reading buf to be overwritten
        if (t + 1 < NTILES) {
            cp_tile(smb, ((t + 1) & 1) ? SM_B1 : SM_B0, gcb0 + (t + 1) * CT);
            CP_COMMIT();
            cp_wait<1>();                  // tile t (and A) now resident
        } else {
            cp_wait<0>();
        }
        __syncthreads();

        const uint32_t smB = smb + ((t & 1) ? SM_B1 : SM_B0);

        float d[4][4][4];
        #pragma unroll
        for (int mf = 0; mf < 4; ++mf)
            #pragma unroll
            for (int nf = 0; nf < 4; ++nf)
                #pragma unroll
                for (int e = 0; e < 4; ++e) d[mf][nf][e] = 0.f;

        #pragma unroll
        for (int ks = 0; ks < DDIM / 16; ++ks) {
            const int k0 = ks * 16;
            uint32_t a[4][4];
            #pragma unroll
            for (int mf = 0; mf < 4; ++mf)
                ldsm4(a[mf], smb + SM_A + (uint32_t)(a_row + mf * 16) * SMS_B
                                 + (uint32_t)(k0 + a_kad) * 2);
            uint32_t b[4][2];
            #pragma unroll
            for (int nh = 0; nh < 2; ++nh) {
                uint32_t r4[4];
                ldsm4(r4, smB + (uint32_t)(b_row + nh * 16) * SMS_B
                              + (uint32_t)(k0 + b_kad) * 2);
                b[2 * nh][0] = r4[0]; b[2 * nh][1] = r4[1];
                b[2 * nh + 1][0] = r4[2]; b[2 * nh + 1][1] = r4[3];
            }
            #pragma unroll
            for (int mf = 0; mf < 4; ++mf)
                #pragma unroll
                for (int nf = 0; nf < 4; ++nf)
                    mma16816(d[mf][nf], a[mf], b[nf]);
        }

        // Fused epilogue: rsum += exp(2*sim), diagonal masked (one tile per CTA)
        const bool diag = (gcb0 + t * CT == rb);
        const int cbase = gcb0 + t * CT + wn * 32 + dcol0;
        #pragma unroll
        for (int mf = 0; mf < 4; ++mf) {
            const int r0 = drow0 + mf * 16;
            #pragma unroll
            for (int nf = 0; nf < 4; ++nf) {
                const int c0 = cbase + nf * 8;
                float e0 = __expf(2.0f * d[mf][nf][0]);
                float e1 = __expf(2.0f * d[mf][nf][1]);
                float e2 = __expf(2.0f * d[mf][nf][2]);
                float e3 = __expf(2.0f * d[mf][nf][3]);
                if (diag) {
                    if (c0     == r0    ) e0 = 0.f;
                    if (c0 + 1 == r0    ) e1 = 0.f;
                    if (c0     == r0 + 8) e2 = 0.f;
                    if (c0 + 1 == r0 + 8) e3 = 0.f;
                }
                rsum[mf * 2]     += e0 + e1;
                rsum[mf * 2 + 1] += e2 + e3;
            }
        }
    }

    // Reduce across the quad (lanes sharing the same rows: xor 1, xor 2)
    #pragma unroll
    for (int s = 0; s < 8; ++s) {
        float v = rsum[s];
        v += __shfl_xor_sync(0xffffffffu, v, 1);
        v += __shfl_xor_sync(0xffffffffu, v, 2);
        rsum[s] = v;
    }

    // Cross-warp (4 N-warps) reduce via smem, then store partial row sums.
    __syncthreads();                       // done with A smem; reuse as scratch
    float* red = reinterpret_cast<float*>(sm);     // [4][128]
    if ((lane & 3) == 0) {
        const int q = lane >> 2;
        #pragma unroll
        for (int mf = 0; mf < 4; ++mf)
            #pragma unroll
            for (int h = 0; h < 2; ++h)
                red[wn * RT + wm * 64 + mf * 16 + h * 8 + q] = rsum[mf * 2 + h];
    }
    __syncthreads();
    if (tid < RT) {
        float s = red[tid] + red[RT + tid] + red[2 * RT + tid] + red[3 * RT + tid];
        g_spart[cs * M_TOTAL + rb + tid] = s;
    }
}

// ---------------------------------------------------------------------------
// Kernel D: loss = mean(log(s0+s1) - pos)
// ---------------------------------------------------------------------------
__global__ __launch_bounds__(256) void loss_kernel(float* __restrict__ out)
{
    __shared__ float red[8];
    const int tid = threadIdx.x;
    float acc = 0.f;
    for (int i = tid; i < M_TOTAL; i += 256)
        acc += logf(g_spart[i] + g_spart[M_TOTAL + i]) - g_pos[i];
    #pragma unroll
    for (int o = 16; o > 0; o >>= 1)
        acc += __shfl_xor_sync(0xffffffffu, acc, o);
    if ((tid & 31) == 0) red[tid >> 5] = acc;
    __syncthreads();
    if (tid == 0) {
        float t = 0.f;
        #pragma unroll
        for (int w = 0; w < 8; ++w) t += red[w];
        out[0] = t / (float)M_TOTAL;
    }
}

// ---------------------------------------------------------------------------
extern "C" void kernel_launch(void* const* d_in, const int* in_sizes, int n_in,
                              void* d_out, int out_size)
{
    const float* zis = (const float*)d_in[0];
    const float* zjs = (const float*)d_in[1];
    float* out = (float*)d_out;

    norm_kernel<<<M_TOTAL / 8, 256>>>(zis, zjs);
    pos_kernel<<<N_HALF / 8, 256>>>();

    cudaFuncSetAttribute(simexp_kernel,
                         cudaFuncAttributeMaxDynamicSharedMemorySize, SMEM_BYTES);
    simexp_kernel<<<dim3(M_TOTAL / RT, CSPLIT), 256, SMEM_BYTES>>>();

    loss_kernel<<<1, 256>>>(out);
}

// round 6
// speedup vs baseline: 16.9084x; 1.5546x over previous
#include <cuda_runtime.h>
#include <cuda_bf16.h>
#include <cstdint>
#include <math.h>

// NTXentLoss via mma.sync (HMMA) bf16 GEMM, symmetric-tile version.
// sim is symmetric: only upper-triangular 128x128 tiles are computed; each
// off-diagonal tile contributes exp-sums to both its row block (row sums)
// and its column block (column sums == row sums of the transposed tile).
// Deterministic: partial sums go to per-tile-slot buffers, no atomics.

#define M_TOTAL 8192
#define N_HALF  4096
#define DDIM    256
#define RT      128
#define NT64    (M_TOTAL / RT)           // 64 tile blocks
#define SMS     (DDIM + 8)               // smem row stride in bf16 (pad)
#define SMS_B   (SMS * 2)                // 528 bytes

// Scratch (__device__ globals: allocation-free rule)
__device__ __nv_bfloat16 g_Z[M_TOTAL * DDIM];       // normalized bf16
__device__ float g_pos[M_TOTAL];                    // 2*sim[i, pair] (fp32)
__device__ float g_spart[NT64][M_TOTAL];            // exp-sum partials, slot-unique
__device__ float g_red[32];                         // loss stage-1 partials

// smem layout (bytes)
#define SM_A   0
#define SM_B   (RT * SMS_B)              // 67584
#define SMEM_BYTES (2 * RT * SMS_B)      // 135168

// ---------------- PTX helpers (compute_103-safe subset) ----------------
__device__ __forceinline__ uint32_t smem_to_u32(const void* p) {
    uint32_t a;
    asm("{ .reg .u64 t; cvta.to.shared.u64 t, %1; cvt.u32.u64 %0, t; }"
        : "=r"(a) : "l"(p));
    return a;
}
__device__ __forceinline__ void ldsm4(uint32_t* r, uint32_t addr) {
    asm volatile("ldmatrix.sync.aligned.m8n8.x4.shared.b16 {%0,%1,%2,%3}, [%4];"
                 : "=r"(r[0]), "=r"(r[1]), "=r"(r[2]), "=r"(r[3]) : "r"(addr));
}
__device__ __forceinline__ void mma16816(float* d, const uint32_t* a, const uint32_t* b) {
    asm volatile(
        "mma.sync.aligned.m16n8k16.row.col.f32.bf16.bf16.f32 "
        "{%0,%1,%2,%3}, {%4,%5,%6,%7}, {%8,%9}, {%0,%1,%2,%3};"
        : "+f"(d[0]), "+f"(d[1]), "+f"(d[2]), "+f"(d[3])
        : "r"(a[0]), "r"(a[1]), "r"(a[2]), "r"(a[3]), "r"(b[0]), "r"(b[1]));
}
__device__ __forceinline__ void cp16(uint32_t smaddr, const void* gptr) {
    asm volatile("cp.async.cg.shared.global [%0], [%1], 16;"
                 :: "r"(smaddr), "l"(gptr) : "memory");
}
#define CP_COMMIT() asm volatile("cp.async.commit_group;" ::: "memory")
template <int N>
__device__ __forceinline__ void cp_wait() {
    asm volatile("cp.async.wait_group %0;" :: "n"(N) : "memory");
}

// Copy half (128 k-cols) of a 128-row tile into smem (2048 16B chunks).
__device__ __forceinline__ void cp_half(uint32_t smb, int smoff, int row0, int kofs) {
    const int tid = threadIdx.x;
    #pragma unroll
    for (int it = 0; it < 8; ++it) {
        int idx = it * 256 + tid;
        int r = idx >> 4;
        int c = idx & 15;
        cp16(smb + smoff + r * SMS_B + kofs * 2 + c * 16,
             g_Z + (size_t)(row0 + r) * DDIM + kofs + c * 8);
    }
}

// ---------------------------------------------------------------------------
// Kernel A: normalize + bf16 quantize + fused positive-pair dot.
// One warp per pair (i, i+N). grid 512 x 256.
// ---------------------------------------------------------------------------
__global__ __launch_bounds__(256) void norm_kernel(const float* __restrict__ zis,
                                                   const float* __restrict__ zjs)
{
    const int wid = threadIdx.x >> 5, lane = threadIdx.x & 31;
    const int i = blockIdx.x * 8 + wid;                 // pair index 0..4095
    const float* sj = zjs + (size_t)i * DDIM;           // reps row i
    const float* si = zis + (size_t)i * DDIM;           // reps row i + N

    float4 j0 = reinterpret_cast<const float4*>(sj)[lane];
    float4 j1 = reinterpret_cast<const float4*>(sj)[lane + 32];
    float4 i0 = reinterpret_cast<const float4*>(si)[lane];
    float4 i1 = reinterpret_cast<const float4*>(si)[lane + 32];

    float ssj = j0.x*j0.x + j0.y*j0.y + j0.z*j0.z + j0.w*j0.w
              + j1.x*j1.x + j1.y*j1.y + j1.z*j1.z + j1.w*j1.w;
    float ssi = i0.x*i0.x + i0.y*i0.y + i0.z*i0.z + i0.w*i0.w
              + i1.x*i1.x + i1.y*i1.y + i1.z*i1.z + i1.w*i1.w;
    float dot = j0.x*i0.x + j0.y*i0.y + j0.z*i0.z + j0.w*i0.w
              + j1.x*i1.x + j1.y*i1.y + j1.z*i1.z + j1.w*i1.w;
    #pragma unroll
    for (int o = 16; o > 0; o >>= 1) {
        ssj += __shfl_xor_sync(0xffffffffu, ssj, o);
        ssi += __shfl_xor_sync(0xffffffffu, ssi, o);
        dot += __shfl_xor_sync(0xffffffffu, dot, o);
    }
    float invj = 1.0f / fmaxf(sqrtf(ssj), 1e-8f);
    float invi = 1.0f / fmaxf(sqrtf(ssi), 1e-8f);
    if (lane == 0) {
        float p = 2.0f * dot * invi * invj;
        g_pos[i] = p;
        g_pos[i + N_HALF] = p;
    }
    __nv_bfloat162* dj = reinterpret_cast<__nv_bfloat162*>(g_Z + (size_t)i * DDIM);
    __nv_bfloat162* di = reinterpret_cast<__nv_bfloat162*>(g_Z + (size_t)(i + N_HALF) * DDIM);
    dj[lane*2+0]    = __floats2bfloat162_rn(j0.x*invj, j0.y*invj);
    dj[lane*2+1]    = __floats2bfloat162_rn(j0.z*invj, j0.w*invj);
    dj[64+lane*2+0] = __floats2bfloat162_rn(j1.x*invj, j1.y*invj);
    dj[64+lane*2+1] = __floats2bfloat162_rn(j1.z*invj, j1.w*invj);
    di[lane*2+0]    = __floats2bfloat162_rn(i0.x*invi, i0.y*invi);
    di[lane*2+1]    = __floats2bfloat162_rn(i0.z*invi, i0.w*invi);
    di[64+lane*2+0] = __floats2bfloat162_rn(i1.x*invi, i1.y*invi);
    di[64+lane*2+1] = __floats2bfloat162_rn(i1.z*invi, i1.w*invi);
}

// ---------------------------------------------------------------------------
// Kernel B: one 128x128 upper-triangular tile per CTA. grid (64, 64), J>=I.
// 256 threads = 8 warps in 2(M) x 4(N); warp tile 64x32.
// 2-phase k-split cp.async prefetch overlaps load with first compute half.
// Epilogue: exp(2*sim); row sums -> g_spart[J][I*128+r];
//           col sums (I!=J) -> g_spart[I][J*128+c]. Diagonal masked on I==J.
// ---------------------------------------------------------------------------
__global__ __launch_bounds__(256) void simexp_kernel()
{
    const int I = blockIdx.x, J = blockIdx.y;
    if (J < I) return;
    const bool diagT = (I == J);

    extern __shared__ char sm[];
    const uint32_t smb = smem_to_u32(sm);
    const int tid = threadIdx.x;
    const int wid = tid >> 5;
    const int lane = tid & 31;
    const int wm = wid >> 2;              // 0..1 (M)
    const int wn = wid & 3;               // 0..3 (N)
    const int rb = I * RT;
    const int cb = J * RT;

    // ldmatrix per-thread addressing (validated in round 5):
    const int a_row = wm * 64 + (lane & 7) + ((lane >> 3) & 1) * 8;
    const int a_kad = (lane >> 4) * 8;
    const int b_row = wn * 32 + (lane & 7) + ((lane >> 4) & 1) * 8;
    const int b_kad = ((lane >> 3) & 1) * 8;

    // Prefetch: k-half 0 (group 0), k-half 1 (group 1)
    cp_half(smb, SM_A, rb, 0);
    if (!diagT) cp_half(smb, SM_B, cb, 0);
    CP_COMMIT();
    cp_half(smb, SM_A, rb, 128);
    if (!diagT) cp_half(smb, SM_B, cb, 128);
    CP_COMMIT();

    const uint32_t smA = smb + SM_A;
    const uint32_t smB = diagT ? smA : (smb + SM_B);

    float d[4][4][4];
    #pragma unroll
    for (int mf = 0; mf < 4; ++mf)
        #pragma unroll
        for (int nf = 0; nf < 4; ++nf)
            #pragma unroll
            for (int e = 0; e < 4; ++e) d[mf][nf][e] = 0.f;

    #pragma unroll
    for (int ph = 0; ph < 2; ++ph) {
        if (ph == 0) { cp_wait<1>(); } else { cp_wait<0>(); }
        __syncthreads();
        #pragma unroll
        for (int ks = 0; ks < 8; ++ks) {
            const int k0 = ph * 128 + ks * 16;
            uint32_t a[4][4];
            #pragma unroll
            for (int mf = 0; mf < 4; ++mf)
                ldsm4(a[mf], smA + (uint32_t)(a_row + mf * 16) * SMS_B
                                 + (uint32_t)(k0 + a_kad) * 2);
            uint32_t b[4][2];
            #pragma unroll
            for (int nh = 0; nh < 2; ++nh) {
                uint32_t r4[4];
                ldsm4(r4, smB + (uint32_t)(b_row + nh * 16) * SMS_B
                              + (uint32_t)(k0 + b_kad) * 2);
                b[2*nh][0] = r4[0]; b[2*nh][1] = r4[1];
                b[2*nh+1][0] = r4[2]; b[2*nh+1][1] = r4[3];
            }
            #pragma unroll
            for (int mf = 0; mf < 4; ++mf)
                #pragma unroll
                for (int nf = 0; nf < 4; ++nf)
                    mma16816(d[mf][nf], a[mf], b[nf]);
        }
    }

    // Epilogue: exp(2*sim); accumulate row sums and column sums.
    // Thread covers rows: wm*64 + mf*16 + h*8 + (lane>>2), h in {0,1}
    //            cols: wn*32 + nf*8 + 2*(lane&3) + e2, e2 in {0,1}
    const int qrow = lane >> 2;
    const int drow0 = rb + wm * 64 + qrow;
    const int dcol0 = cb + wn * 32 + 2 * (lane & 3);

    float rsum[8], csum[8];
    #pragma unroll
    for (int s = 0; s < 8; ++s) { rsum[s] = 0.f; csum[s] = 0.f; }

    #pragma unroll
    for (int mf = 0; mf < 4; ++mf) {
        const int r0 = drow0 + mf * 16;
        #pragma unroll
        for (int nf = 0; nf < 4; ++nf) {
            const int c0 = dcol0 + nf * 8;
            float e0 = __expf(2.0f * d[mf][nf][0]);
            float e1 = __expf(2.0f * d[mf][nf][1]);
            float e2 = __expf(2.0f * d[mf][nf][2]);
            float e3 = __expf(2.0f * d[mf][nf][3]);
            if (diagT) {
                if (c0     == r0    ) e0 = 0.f;
                if (c0 + 1 == r0    ) e1 = 0.f;
                if (c0     == r0 + 8) e2 = 0.f;
                if (c0 + 1 == r0 + 8) e3 = 0.f;
            }
            rsum[mf*2]   += e0 + e1;
            rsum[mf*2+1] += e2 + e3;
            csum[nf*2]   += e0 + e2;
            csum[nf*2+1] += e1 + e3;
        }
    }

    // rsum: reduce over quad lanes sharing rows (xor 1, 2)
    #pragma unroll
    for (int s = 0; s < 8; ++s) {
        float v = rsum[s];
        v += __shfl_xor_sync(0xffffffffu, v, 1);
        v += __shfl_xor_sync(0xffffffffu, v, 2);
        rsum[s] = v;
    }
    // csum: reduce over lanes sharing cols (xor 4, 8, 16)
    #pragma unroll
    for (int s = 0; s < 8; ++s) {
        float v = csum[s];
        v += __shfl_xor_sync(0xffffffffu, v, 4);
        v += __shfl_xor_sync(0xffffffffu, v, 8);
        v += __shfl_xor_sync(0xffffffffu, v, 16);
        csum[s] = v;
    }

    __syncthreads();                       // compute done; reuse smem as scratch
    float* redR = reinterpret_cast<float*>(sm);          // [4][128]
    float* redC = redR + 4 * RT;                         // [2][128]
    if ((lane & 3) == 0) {
        #pragma unroll
        for (int mf = 0; mf < 4; ++mf)
            #pragma unroll
            for (int h = 0; h < 2; ++h)
                redR[wn * RT + wm * 64 + mf * 16 + h * 8 + qrow] = rsum[mf*2+h];
    }
    if (lane < 4) {
        #pragma unroll
        for (int nf = 0; nf < 4; ++nf)
            #pragma unroll
            for (int e2 = 0; e2 < 2; ++e2)
                redC[wm * RT + wn * 32 + nf * 8 + 2 * lane + e2] = csum[nf*2+e2];
    }
    __syncthreads();
    if (tid < RT) {
        float rs = redR[tid] + redR[RT+tid] + redR[2*RT+tid] + redR[3*RT+tid];
        g_spart[J][rb + tid] = rs;
        if (!diagT) {
            float cs = redC[tid] + redC[RT + tid];
            g_spart[I][cb + tid] = cs;
        }
    }
}

// ---------------------------------------------------------------------------
// Kernel D1: per-row log-sum minus pos, 32 deterministic block partials.
// ---------------------------------------------------------------------------
__global__ __launch_bounds__(256) void lossA_kernel()
{
    __shared__ float red[8];
    const int tid = threadIdx.x;
    const int i = blockIdx.x * 256 + tid;       // exactly 8192 threads
    float s = 0.f;
    #pragma unroll 8
    for (int t = 0; t < NT64; ++t)
        s += g_spart[t][i];
    float acc = __logf(s) - g_pos[i];
    #pragma unroll
    for (int o = 16; o > 0; o >>= 1)
        acc += __shfl_xor_sync(0xffffffffu, acc, o);
    if ((tid & 31) == 0) red[tid >> 5] = acc;
    __syncthreads();
    if (tid == 0) {
        float t = 0.f;
        #pragma unroll
        for (int w = 0; w < 8; ++w) t += red[w];
        g_red[blockIdx.x] = t;
    }
}

// ---------------------------------------------------------------------------
// Kernel D2: final 32 -> scalar.
// ---------------------------------------------------------------------------
__global__ void lossB_kernel(float* __restrict__ out)
{
    const int lane = threadIdx.x;
    float v = g_red[lane];
    #pragma unroll
    for (int o = 16; o > 0; o >>= 1)
        v += __shfl_xor_sync(0xffffffffu, v, o);
    if (lane == 0) out[0] = v / (float)M_TOTAL;
}

// ---------------------------------------------------------------------------
extern "C" void kernel_launch(void* const* d_in, const int* in_sizes, int n_in,
                              void* d_out, int out_size)
{
    const float* zis = (const float*)d_in[0];
    const float* zjs = (const float*)d_in[1];
    float* out = (float*)d_out;

    norm_kernel<<<N_HALF / 8, 256>>>(zis, zjs);

    cudaFuncSetAttribute(simexp_kernel,
                         cudaFuncAttributeMaxDynamicSharedMemorySize, SMEM_BYTES);
    simexp_kernel<<<dim3(NT64, NT64), 256, SMEM_BYTES>>>();

    lossA_kernel<<<32, 256>>>();
    lossB_kernel<<<1, 32>>>(out);
}

// round 7
// speedup vs baseline: 17.6547x; 1.0441x over previous
#include <cuda_runtime.h>
#include <cuda_bf16.h>
#include <cstdint>
#include <math.h>

// NTXentLoss via mma.sync (HMMA) bf16 GEMM, symmetric upper-triangular tiles,
// strip-mined: each CTA owns up to 4 consecutive J-tiles of one row block I.
// A tile stays resident in smem; B tiles are double-buffered and prefetched
// with cp.async one tile ahead. Deterministic slot-unique partial sums.

#define M_TOTAL 8192
#define N_HALF  4096
#define DDIM    256
#define RT      128
#define NT64    (M_TOTAL / RT)           // 64 tile blocks
#define STRIP   4                        // tiles per CTA (max)
#define SMS     (DDIM + 8)               // smem row stride in bf16 (pad)
#define SMS_B   (SMS * 2)                // 528 bytes

// Scratch (__device__ globals: allocation-free rule)
__device__ __nv_bfloat16 g_Z[M_TOTAL * DDIM];       // normalized bf16
__device__ float g_pos[M_TOTAL];                    // 2*sim[i, pair] (fp32)
__device__ float g_spart[NT64][M_TOTAL];            // exp-sum partials, slot-unique
__device__ float g_red[32];                         // loss stage-1 partials

// smem layout (bytes)
#define SM_A   0
#define SM_B0  (RT * SMS_B)              // 67584
#define SM_B1  (2 * RT * SMS_B)          // 135168
#define SMEM_BYTES (3 * RT * SMS_B)      // 202752

// ---------------- PTX helpers (compute_103-safe subset) ----------------
__device__ __forceinline__ uint32_t smem_to_u32(const void* p) {
    uint32_t a;
    asm("{ .reg .u64 t; cvta.to.shared.u64 t, %1; cvt.u32.u64 %0, t; }"
        : "=r"(a) : "l"(p));
    return a;
}
__device__ __forceinline__ void ldsm4(uint32_t* r, uint32_t addr) {
    asm volatile("ldmatrix.sync.aligned.m8n8.x4.shared.b16 {%0,%1,%2,%3}, [%4];"
                 : "=r"(r[0]), "=r"(r[1]), "=r"(r[2]), "=r"(r[3]) : "r"(addr));
}
__device__ __forceinline__ void mma16816(float* d, const uint32_t* a, const uint32_t* b) {
    asm volatile(
        "mma.sync.aligned.m16n8k16.row.col.f32.bf16.bf16.f32 "
        "{%0,%1,%2,%3}, {%4,%5,%6,%7}, {%8,%9}, {%0,%1,%2,%3};"
        : "+f"(d[0]), "+f"(d[1]), "+f"(d[2]), "+f"(d[3])
        : "r"(a[0]), "r"(a[1]), "r"(a[2]), "r"(a[3]), "r"(b[0]), "r"(b[1]));
}
__device__ __forceinline__ void cp16(uint32_t smaddr, const void* gptr) {
    asm volatile("cp.async.cg.shared.global [%0], [%1], 16;"
                 :: "r"(smaddr), "l"(gptr) : "memory");
}
#define CP_COMMIT() asm volatile("cp.async.commit_group;" ::: "memory")
template <int N>
__device__ __forceinline__ void cp_wait() {
    asm volatile("cp.async.wait_group %0;" :: "n"(N) : "memory");
}

// Async-copy one full 128x256 bf16 tile into smem (4096 16B chunks).
__device__ __forceinline__ void cp_tile(uint32_t smb, int smoff, int row0) {
    const int tid = threadIdx.x;
    #pragma unroll
    for (int it = 0; it < 16; ++it) {
        int idx = it * 256 + tid;
        int r = idx >> 5;
        int c = idx & 31;
        cp16(smb + smoff + r * SMS_B + c * 16,
             g_Z + (size_t)(row0 + r) * DDIM + c * 8);
    }
}

// ---------------------------------------------------------------------------
// Kernel A: normalize + bf16 quantize + fused positive-pair dot.
// One warp per pair (i, i+N).
// ---------------------------------------------------------------------------
__global__ __launch_bounds__(256) void norm_kernel(const float* __restrict__ zis,
                                                   const float* __restrict__ zjs)
{
    const int wid = threadIdx.x >> 5, lane = threadIdx.x & 31;
    const int i = blockIdx.x * 8 + wid;                 // pair index 0..4095
    const float* sj = zjs + (size_t)i * DDIM;
    const float* si = zis + (size_t)i * DDIM;

    float4 j0 = reinterpret_cast<const float4*>(sj)[lane];
    float4 j1 = reinterpret_cast<const float4*>(sj)[lane + 32];
    float4 i0 = reinterpret_cast<const float4*>(si)[lane];
    float4 i1 = reinterpret_cast<const float4*>(si)[lane + 32];

    float ssj = j0.x*j0.x + j0.y*j0.y + j0.z*j0.z + j0.w*j0.w
              + j1.x*j1.x + j1.y*j1.y + j1.z*j1.z + j1.w*j1.w;
    float ssi = i0.x*i0.x + i0.y*i0.y + i0.z*i0.z + i0.w*i0.w
              + i1.x*i1.x + i1.y*i1.y + i1.z*i1.z + i1.w*i1.w;
    float dot = j0.x*i0.x + j0.y*i0.y + j0.z*i0.z + j0.w*i0.w
              + j1.x*i1.x + j1.y*i1.y + j1.z*i1.z + j1.w*i1.w;
    #pragma unroll
    for (int o = 16; o > 0; o >>= 1) {
        ssj += __shfl_xor_sync(0xffffffffu, ssj, o);
        ssi += __shfl_xor_sync(0xffffffffu, ssi, o);
        dot += __shfl_xor_sync(0xffffffffu, dot, o);
    }
    float invj = 1.0f / fmaxf(sqrtf(ssj), 1e-8f);
    float invi = 1.0f / fmaxf(sqrtf(ssi), 1e-8f);
    if (lane == 0) {
        float p = 2.0f * dot * invi * invj;
        g_pos[i] = p;
        g_pos[i + N_HALF] = p;
    }
    __nv_bfloat162* dj = reinterpret_cast<__nv_bfloat162*>(g_Z + (size_t)i * DDIM);
    __nv_bfloat162* di = reinterpret_cast<__nv_bfloat162*>(g_Z + (size_t)(i + N_HALF) * DDIM);
    dj[lane*2+0]    = __floats2bfloat162_rn(j0.x*invj, j0.y*invj);
    dj[lane*2+1]    = __floats2bfloat162_rn(j0.z*invj, j0.w*invj);
    dj[64+lane*2+0] = __floats2bfloat162_rn(j1.x*invj, j1.y*invj);
    dj[64+lane*2+1] = __floats2bfloat162_rn(j1.z*invj, j1.w*invj);
    di[lane*2+0]    = __floats2bfloat162_rn(i0.x*invi, i0.y*invi);
    di[lane*2+1]    = __floats2bfloat162_rn(i0.z*invi, i0.w*invi);
    di[64+lane*2+0] = __floats2bfloat162_rn(i1.x*invi, i1.y*invi);
    di[64+lane*2+1] = __floats2bfloat162_rn(i1.z*invi, i1.w*invi);
}

// ---------------------------------------------------------------------------
// Kernel B: strip of up to 4 upper-triangular tiles per CTA.
// grid (16, 64): c = blockIdx.x (strip within row block), I = blockIdx.y.
// Tiles J = I+4c .. min(I+4c+3, 63). A resident, B double-buffered/prefetched.
// ---------------------------------------------------------------------------
__global__ __launch_bounds__(256) void simexp_kernel()
{
    const int I = blockIdx.y;
    const int J0 = I + STRIP * blockIdx.x;
    if (J0 >= NT64) return;
    const int nt = min(STRIP, NT64 - J0);

    extern __shared__ char sm[];
    const uint32_t smb = smem_to_u32(sm);
    const int tid = threadIdx.x;
    const int wid = tid >> 5;
    const int lane = tid & 31;
    const int wm = wid >> 2;              // 0..1 (M)
    const int wn = wid & 3;               // 0..3 (N)
    const int rb = I * RT;

    // ldmatrix per-thread addressing (validated round 5):
    const int a_row = wm * 64 + (lane & 7) + ((lane >> 3) & 1) * 8;
    const int a_kad = (lane >> 4) * 8;
    const int b_row = wn * 32 + (lane & 7) + ((lane >> 4) & 1) * 8;
    const int b_kad = ((lane >> 3) & 1) * 8;

    const uint32_t smA = smb + SM_A;

    // Prologue: A + (B of first tile, unless it is the diagonal tile)
    cp_tile(smb, SM_A, rb);
    if (J0 != I) cp_tile(smb, SM_B0, J0 * RT);
    CP_COMMIT();

    const int qrow = lane >> 2;
    const int drow0 = rb + wm * 64 + qrow;

    int buf = 0;
    for (int s = 0; s < nt; ++s) {
        const int J = J0 + s;
        const int cb = J * RT;
        const bool diagT = (J == I);

        cp_wait<0>();                      // current tile's data resident
        __syncthreads();

        if (s + 1 < nt) {                  // prefetch next B into other buffer
            cp_tile(smb, (buf ^ 1) ? SM_B1 : SM_B0, (J + 1) * RT);
            CP_COMMIT();
        }

        const uint32_t smB = diagT ? smA : (smb + (buf ? SM_B1 : SM_B0));

        float d[4][4][4];
        #pragma unroll
        for (int mf = 0; mf < 4; ++mf)
            #pragma unroll
            for (int nf = 0; nf < 4; ++nf)
                #pragma unroll
                for (int e = 0; e < 4; ++e) d[mf][nf][e] = 0.f;

        #pragma unroll
        for (int ks = 0; ks < DDIM / 16; ++ks) {
            const int k0 = ks * 16;
            uint32_t a[4][4];
            #pragma unroll
            for (int mf = 0; mf < 4; ++mf)
                ldsm4(a[mf], smA + (uint32_t)(a_row + mf * 16) * SMS_B
                                 + (uint32_t)(k0 + a_kad) * 2);
            uint32_t b[4][2];
            #pragma unroll
            for (int nh = 0; nh < 2; ++nh) {
                uint32_t r4[4];
                ldsm4(r4, smB + (uint32_t)(b_row + nh * 16) * SMS_B
                              + (uint32_t)(k0 + b_kad) * 2);
                b[2*nh][0] = r4[0]; b[2*nh][1] = r4[1];
                b[2*nh+1][0] = r4[2]; b[2*nh+1][1] = r4[3];
            }
            #pragma unroll
            for (int mf = 0; mf < 4; ++mf)
                #pragma unroll
                for (int nf = 0; nf < 4; ++nf)
                    mma16816(d[mf][nf], a[mf], b[nf]);
        }

        // Epilogue: exp(2*sim); row sums + column sums.
        const int dcol0 = cb + wn * 32 + 2 * (lane & 3);
        float rsum[8], csum[8];
        #pragma unroll
        for (int q = 0; q < 8; ++q) { rsum[q] = 0.f; csum[q] = 0.f; }

        #pragma unroll
        for (int mf = 0; mf < 4; ++mf) {
            const int r0 = drow0 + mf * 16;
            #pragma unroll
            for (int nf = 0; nf < 4; ++nf) {
                const int c0 = dcol0 + nf * 8;
                float e0 = __expf(2.0f * d[mf][nf][0]);
                float e1 = __expf(2.0f * d[mf][nf][1]);
                float e2 = __expf(2.0f * d[mf][nf][2]);
                float e3 = __expf(2.0f * d[mf][nf][3]);
                if (diagT) {
                    if (c0     == r0    ) e0 = 0.f;
                    if (c0 + 1 == r0    ) e1 = 0.f;
                    if (c0     == r0 + 8) e2 = 0.f;
                    if (c0 + 1 == r0 + 8) e3 = 0.f;
                }
                rsum[mf*2]   += e0 + e1;
                rsum[mf*2+1] += e2 + e3;
                csum[nf*2]   += e0 + e2;
                csum[nf*2+1] += e1 + e3;
            }
        }

        #pragma unroll
        for (int q = 0; q < 8; ++q) {
            float v = rsum[q];
            v += __shfl_xor_sync(0xffffffffu, v, 1);
            v += __shfl_xor_sync(0xffffffffu, v, 2);
            rsum[q] = v;
            float w = csum[q];
            w += __shfl_xor_sync(0xffffffffu, w, 4);
            w += __shfl_xor_sync(0xffffffffu, w, 8);
            w += __shfl_xor_sync(0xffffffffu, w, 16);
            csum[q] = w;
        }

        // Scratch: reuse the just-consumed B buffer (A stays resident).
        // Safe: next prefetch targets the other buffer; this region is not
        // reloaded until tile s+2, whose cp.async is issued after the next
        // loop-top __syncthreads.
        __syncthreads();                   // all MMA reads of smB done
        float* redR = reinterpret_cast<float*>(sm + (buf ? SM_B1 : SM_B0)); // [4][128]
        float* redC = redR + 4 * RT;                                        // [2][128]
        if ((lane & 3) == 0) {
            #pragma unroll
            for (int mf = 0; mf < 4; ++mf)
                #pragma unroll
                for (int h = 0; h < 2; ++h)
                    redR[wn * RT + wm * 64 + mf * 16 + h * 8 + qrow] = rsum[mf*2+h];
        }
        if (lane < 4) {
            #pragma unroll
            for (int nf = 0; nf < 4; ++nf)
                #pragma unroll
                for (int e2 = 0; e2 < 2; ++e2)
                    redC[wm * RT + wn * 32 + nf * 8 + 2 * lane + e2] = csum[nf*2+e2];
        }
        __syncthreads();
        if (tid < RT) {
            float rs = redR[tid] + redR[RT+tid] + redR[2*RT+tid] + redR[3*RT+tid];
            g_spart[J][rb + tid] = rs;
            if (!diagT) {
                float cs = redC[tid] + redC[RT + tid];
                g_spart[I][cb + tid] = cs;
            }
        }

        if (s + 1 < nt) buf ^= 1;
    }
}

// ---------------------------------------------------------------------------
// Kernel D1: per-row log-sum minus pos, 32 deterministic block partials.
// ---------------------------------------------------------------------------
__global__ __launch_bounds__(256) void lossA_kernel()
{
    __shared__ float red[8];
    const int tid = threadIdx.x;
    const int i = blockIdx.x * 256 + tid;       // exactly 8192 threads
    float s = 0.f;
    #pragma unroll 8
    for (int t = 0; t < NT64; ++t)
        s += g_spart[t][i];
    float acc = __logf(s) - g_pos[i];
    #pragma unroll
    for (int o = 16; o > 0; o >>= 1)
        acc += __shfl_xor_sync(0xffffffffu, acc, o);
    if ((tid & 31) == 0) red[tid >> 5] = acc;
    __syncthreads();
    if (tid == 0) {
        float t = 0.f;
        #pragma unroll
        for (int w = 0; w < 8; ++w) t += red[w];
        g_red[blockIdx.x] = t;
    }
}

// ---------------------------------------------------------------------------
// Kernel D2: final 32 -> scalar.
// ---------------------------------------------------------------------------
__global__ void lossB_kernel(float* __restrict__ out)
{
    const int lane = threadIdx.x;
    float v = g_red[lane];
    #pragma unroll
    for (int o = 16; o > 0; o >>= 1)
        v += __shfl_xor_sync(0xffffffffu, v, o);
    if (lane == 0) out[0] = v / (float)M_TOTAL;
}

// ---------------------------------------------------------------------------
extern "C" void kernel_launch(void* const* d_in, const int* in_sizes, int n_in,
                              void* d_out, int out_size)
{
    const float* zis = (const float*)d_in[0];
    const float* zjs = (const float*)d_in[1];
    float* out = (float*)d_out;

    norm_kernel<<<N_HALF / 8, 256>>>(zis, zjs);

    cudaFuncSetAttribute(simexp_kernel,
                         cudaFuncAttributeMaxDynamicSharedMemorySize, SMEM_BYTES);
    simexp_kernel<<<dim3(16, NT64), 256, SMEM_BYTES>>>();

    lossA_kernel<<<32, 256>>>();
    lossB_kernel<<<1, 32>>>(out);
}

// round 8
// speedup vs baseline: 18.0531x; 1.0226x over previous
#include <cuda_runtime.h>
#include <cuda_bf16.h>
#include <cstdint>
#include <math.h>

// NTXentLoss via mma.sync (HMMA) bf16 GEMM, symmetric upper-triangular tiles,
// strip-mined (4 J-tiles per CTA). Round 8: strip-persistent row sums,
// named-barrier pairwise column reduction (1 CTA sync per tile), ex2.approx,
// merged loss kernel (threadfence reduction).

#define M_TOTAL 8192
#define N_HALF  4096
#define DDIM    256
#define RT      128
#define NT64    (M_TOTAL / RT)           // 64 tile blocks
#define STRIP   4
#define SMS     (DDIM + 8)               // smem row stride in bf16 (pad)
#define SMS_B   (SMS * 2)                // 528 bytes
#define LOG2E2  2.885390081777927f       // 2 / ln(2) : exp(2x) = 2^(x*LOG2E2)

// Scratch (__device__ globals: allocation-free rule)
__device__ __nv_bfloat16 g_Z[M_TOTAL * DDIM];       // normalized bf16
__device__ float g_pos[M_TOTAL];                    // 2*sim[i, pair] (fp32)
__device__ float g_spart[NT64][M_TOTAL];            // partial sums, slot-unique
__device__ float g_red[32];                         // loss block partials
__device__ unsigned int g_ctr;                      // loss completion counter

// smem layout (bytes)
#define SM_A    0
#define SM_B0   (RT * SMS_B)             // 67584
#define SM_B1   (2 * RT * SMS_B)         // 135168
#define SM_CSC  (3 * RT * SMS_B)         // 202752: csc[4][2][32] floats
#define SMEM_BYTES (SM_CSC + 4 * 2 * 32 * 4)

// ---------------- PTX helpers (compute_103-safe subset) ----------------
__device__ __forceinline__ uint32_t smem_to_u32(const void* p) {
    uint32_t a;
    asm("{ .reg .u64 t; cvta.to.shared.u64 t, %1; cvt.u32.u64 %0, t; }"
        : "=r"(a) : "l"(p));
    return a;
}
__device__ __forceinline__ void ldsm4(uint32_t* r, uint32_t addr) {
    asm volatile("ldmatrix.sync.aligned.m8n8.x4.shared.b16 {%0,%1,%2,%3}, [%4];"
                 : "=r"(r[0]), "=r"(r[1]), "=r"(r[2]), "=r"(r[3]) : "r"(addr));
}
__device__ __forceinline__ void mma16816(float* d, const uint32_t* a, const uint32_t* b) {
    asm volatile(
        "mma.sync.aligned.m16n8k16.row.col.f32.bf16.bf16.f32 "
        "{%0,%1,%2,%3}, {%4,%5,%6,%7}, {%8,%9}, {%0,%1,%2,%3};"
        : "+f"(d[0]), "+f"(d[1]), "+f"(d[2]), "+f"(d[3])
        : "r"(a[0]), "r"(a[1]), "r"(a[2]), "r"(a[3]), "r"(b[0]), "r"(b[1]));
}
__device__ __forceinline__ void cp16(uint32_t smaddr, const void* gptr) {
    asm volatile("cp.async.cg.shared.global [%0], [%1], 16;"
                 :: "r"(smaddr), "l"(gptr) : "memory");
}
#define CP_COMMIT() asm volatile("cp.async.commit_group;" ::: "memory")
template <int N>
__device__ __forceinline__ void cp_wait() {
    asm volatile("cp.async.wait_group %0;" :: "n"(N) : "memory");
}
__device__ __forceinline__ void barpair(int id) {    // 2-warp named barrier
    asm volatile("bar.sync %0, 64;" :: "r"(id) : "memory");
}
__device__ __forceinline__ float ex2(float x) {
    float r;
    asm("ex2.approx.f32 %0, %1;" : "=f"(r) : "f"(x));
    return r;
}

// Async-copy one full 128x256 bf16 tile into smem (4096 16B chunks).
__device__ __forceinline__ void cp_tile(uint32_t smb, int smoff, int row0) {
    const int tid = threadIdx.x;
    #pragma unroll
    for (int it = 0; it < 16; ++it) {
        int idx = it * 256 + tid;
        int r = idx >> 5;
        int c = idx & 31;
        cp16(smb + smoff + r * SMS_B + c * 16,
             g_Z + (size_t)(row0 + r) * DDIM + c * 8);
    }
}

// ---------------------------------------------------------------------------
// Kernel A: normalize + bf16 quantize + fused positive-pair dot.
// ---------------------------------------------------------------------------
__global__ __launch_bounds__(256) void norm_kernel(const float* __restrict__ zis,
                                                   const float* __restrict__ zjs)
{
    const int wid = threadIdx.x >> 5, lane = threadIdx.x & 31;
    const int i = blockIdx.x * 8 + wid;                 // pair index 0..4095
    const float* sj = zjs + (size_t)i * DDIM;
    const float* si = zis + (size_t)i * DDIM;

    float4 j0 = reinterpret_cast<const float4*>(sj)[lane];
    float4 j1 = reinterpret_cast<const float4*>(sj)[lane + 32];
    float4 i0 = reinterpret_cast<const float4*>(si)[lane];
    float4 i1 = reinterpret_cast<const float4*>(si)[lane + 32];

    float ssj = j0.x*j0.x + j0.y*j0.y + j0.z*j0.z + j0.w*j0.w
              + j1.x*j1.x + j1.y*j1.y + j1.z*j1.z + j1.w*j1.w;
    float ssi = i0.x*i0.x + i0.y*i0.y + i0.z*i0.z + i0.w*i0.w
              + i1.x*i1.x + i1.y*i1.y + i1.z*i1.z + i1.w*i1.w;
    float dot = j0.x*i0.x + j0.y*i0.y + j0.z*i0.z + j0.w*i0.w
              + j1.x*i1.x + j1.y*i1.y + j1.z*i1.z + j1.w*i1.w;
    #pragma unroll
    for (int o = 16; o > 0; o >>= 1) {
        ssj += __shfl_xor_sync(0xffffffffu, ssj, o);
        ssi += __shfl_xor_sync(0xffffffffu, ssi, o);
        dot += __shfl_xor_sync(0xffffffffu, dot, o);
    }
    float invj = 1.0f / fmaxf(sqrtf(ssj), 1e-8f);
    float invi = 1.0f / fmaxf(sqrtf(ssi), 1e-8f);
    if (lane == 0) {
        float p = 2.0f * dot * invi * invj;
        g_pos[i] = p;
        g_pos[i + N_HALF] = p;
    }
    __nv_bfloat162* dj = reinterpret_cast<__nv_bfloat162*>(g_Z + (size_t)i * DDIM);
    __nv_bfloat162* di = reinterpret_cast<__nv_bfloat162*>(g_Z + (size_t)(i + N_HALF) * DDIM);
    dj[lane*2+0]    = __floats2bfloat162_rn(j0.x*invj, j0.y*invj);
    dj[lane*2+1]    = __floats2bfloat162_rn(j0.z*invj, j0.w*invj);
    dj[64+lane*2+0] = __floats2bfloat162_rn(j1.x*invj, j1.y*invj);
    dj[64+lane*2+1] = __floats2bfloat162_rn(j1.z*invj, j1.w*invj);
    di[lane*2+0]    = __floats2bfloat162_rn(i0.x*invi, i0.y*invi);
    di[lane*2+1]    = __floats2bfloat162_rn(i0.z*invi, i0.w*invi);
    di[64+lane*2+0] = __floats2bfloat162_rn(i1.x*invi, i1.y*invi);
    di[64+lane*2+1] = __floats2bfloat162_rn(i1.z*invi, i1.w*invi);
}

// ---------------------------------------------------------------------------
// Kernel B: strip of up to 4 upper-triangular tiles per CTA.
// grid (16, 64): c = blockIdx.x, I = blockIdx.y; J = I+4c ... (early exit).
// One CTA sync per tile; column reduce via 2-warp named barriers; row sums
// strip-persistent in registers, written once per strip to slot J0.
// ---------------------------------------------------------------------------
__global__ __launch_bounds__(256) void simexp_kernel()
{
    const int I = blockIdx.y;
    const int J0 = I + STRIP * blockIdx.x;
    if (J0 >= NT64) return;
    const int nt = min(STRIP, NT64 - J0);

    extern __shared__ char sm[];
    const uint32_t smb = smem_to_u32(sm);
    const int tid = threadIdx.x;
    const int wid = tid >> 5;
    const int lane = tid & 31;
    const int wm = wid >> 2;              // 0..1 (M)
    const int wn = wid & 3;               // 0..3 (N)
    const int rb = I * RT;

    const int a_row = wm * 64 + (lane & 7) + ((lane >> 3) & 1) * 8;
    const int a_kad = (lane >> 4) * 8;
    const int b_row = wn * 32 + (lane & 7) + ((lane >> 4) & 1) * 8;
    const int b_kad = ((lane >> 3) & 1) * 8;

    const uint32_t smA = smb + SM_A;
    float* csc = reinterpret_cast<float*>(sm + SM_CSC);   // [4][2][32]

    // Prologue: A + (B of first tile, unless diagonal)
    cp_tile(smb, SM_A, rb);
    if (J0 != I) cp_tile(smb, SM_B0, J0 * RT);
    CP_COMMIT();

    const int qrow = lane >> 2;
    const int drow0 = rb + wm * 64 + qrow;

    float rsum[8];                          // strip-persistent row sums
    #pragma unroll
    for (int q = 0; q < 8; ++q) rsum[q] = 0.f;

    int buf = 0;
    for (int s = 0; s < nt; ++s) {
        const int J = J0 + s;
        const int cb = J * RT;
        const bool diagT = (J == I);

        cp_wait<0>();
        __syncthreads();                    // single CTA sync per tile

        if (s + 1 < nt) {
            cp_tile(smb, (buf ^ 1) ? SM_B1 : SM_B0, (J + 1) * RT);
            CP_COMMIT();
        }

        const uint32_t smB = diagT ? smA : (smb + (buf ? SM_B1 : SM_B0));

        float d[4][4][4];
        #pragma unroll
        for (int mf = 0; mf < 4; ++mf)
            #pragma unroll
            for (int nf = 0; nf < 4; ++nf)
                #pragma unroll
                for (int e = 0; e < 4; ++e) d[mf][nf][e] = 0.f;

        #pragma unroll
        for (int ks = 0; ks < DDIM / 16; ++ks) {
            const int k0 = ks * 16;
            uint32_t a[4][4];
            #pragma unroll
            for (int mf = 0; mf < 4; ++mf)
                ldsm4(a[mf], smA + (uint32_t)(a_row + mf * 16) * SMS_B
                                 + (uint32_t)(k0 + a_kad) * 2);
            uint32_t b[4][2];
            #pragma unroll
            for (int nh = 0; nh < 2; ++nh) {
                uint32_t r4[4];
                ldsm4(r4, smB + (uint32_t)(b_row + nh * 16) * SMS_B
                              + (uint32_t)(k0 + b_kad) * 2);
                b[2*nh][0] = r4[0]; b[2*nh][1] = r4[1];
                b[2*nh+1][0] = r4[2]; b[2*nh+1][1] = r4[3];
            }
            #pragma unroll
            for (int mf = 0; mf < 4; ++mf)
                #pragma unroll
                for (int nf = 0; nf < 4; ++nf)
                    mma16816(d[mf][nf], a[mf], b[nf]);
        }

        // Epilogue: e = 2^(d * 2log2e) = exp(2*sim). Row sums accumulate in
        // registers across the strip; col sums reduced now (warp-pair only).
        const int dcol0 = cb + wn * 32 + 2 * (lane & 3);
        float csum[8];
        #pragma unroll
        for (int q = 0; q < 8; ++q) csum[q] = 0.f;

        #pragma unroll
        for (int mf = 0; mf < 4; ++mf) {
            const int r0 = drow0 + mf * 16;
            #pragma unroll
            for (int nf = 0; nf < 4; ++nf) {
                const int c0 = dcol0 + nf * 8;
                float e0 = ex2(d[mf][nf][0] * LOG2E2);
                float e1 = ex2(d[mf][nf][1] * LOG2E2);
                float e2 = ex2(d[mf][nf][2] * LOG2E2);
                float e3 = ex2(d[mf][nf][3] * LOG2E2);
                if (diagT) {
                    if (c0     == r0    ) e0 = 0.f;
                    if (c0 + 1 == r0    ) e1 = 0.f;
                    if (c0     == r0 + 8) e2 = 0.f;
                    if (c0 + 1 == r0 + 8) e3 = 0.f;
                }
                rsum[mf*2]   += e0 + e1;
                rsum[mf*2+1] += e2 + e3;
                csum[nf*2]   += e0 + e2;
                csum[nf*2+1] += e1 + e3;
            }
        }

        if (!diagT) {
            // reduce csum over lanes sharing a column (xor 4, 8, 16)
            #pragma unroll
            for (int q = 0; q < 8; ++q) {
                float w = csum[q];
                w += __shfl_xor_sync(0xffffffffu, w, 4);
                w += __shfl_xor_sync(0xffffffffu, w, 8);
                w += __shfl_xor_sync(0xffffffffu, w, 16);
                csum[q] = w;
            }
            // cross-wm reduce via 2-warp named barrier (other warps keep going)
            float* my = csc + (wn * 2 + wm) * 32;
            if (lane < 4) {
                #pragma unroll
                for (int nf = 0; nf < 4; ++nf)
                    #pragma unroll
                    for (int e2 = 0; e2 < 2; ++e2)
                        my[nf * 8 + 2 * lane + e2] = csum[nf*2+e2];
            }
            barpair(1 + wn);
            if (wm == 1) {
                float v = csc[(wn*2+0)*32 + lane] + csc[(wn*2+1)*32 + lane];
                g_spart[I][cb + wn * 32 + lane] = v;
            }
        }

        if (s + 1 < nt) buf ^= 1;
    }

    // Strip end: reduce row sums (quad lanes share rows) and write slot J0.
    #pragma unroll
    for (int q = 0; q < 8; ++q) {
        float v = rsum[q];
        v += __shfl_xor_sync(0xffffffffu, v, 1);
        v += __shfl_xor_sync(0xffffffffu, v, 2);
        rsum[q] = v;
    }
    __syncthreads();                        // all mma reads of smA done
    float* redR = reinterpret_cast<float*>(sm);          // [4][128]
    if ((lane & 3) == 0) {
        #pragma unroll
        for (int mf = 0; mf < 4; ++mf)
            #pragma unroll
            for (int h = 0; h < 2; ++h)
                redR[wn * RT + wm * 64 + mf * 16 + h * 8 + qrow] = rsum[mf*2+h];
    }
    __syncthreads();
    if (tid < RT) {
        float rs = redR[tid] + redR[RT+tid] + redR[2*RT+tid] + redR[3*RT+tid];
        g_spart[J0][rb + tid] = rs;
    }
}

// ---------------------------------------------------------------------------
// Kernel D: merged loss (threadfence reduction; deterministic).
// ---------------------------------------------------------------------------
__global__ __launch_bounds__(256) void loss_kernel(float* __restrict__ out)
{
    __shared__ float red[8];
    __shared__ bool amLast;
    const int tid = threadIdx.x;
    const int i = blockIdx.x * 256 + tid;       // exactly 8192 threads
    float s = 0.f;
    #pragma unroll 8
    for (int t = 0; t < NT64; ++t)
        s += g_spart[t][i];
    float acc = __logf(s) - g_pos[i];
    #pragma unroll
    for (int o = 16; o > 0; o >>= 1)
        acc += __shfl_xor_sync(0xffffffffu, acc, o);
    if ((tid & 31) == 0) red[tid >> 5] = acc;
    __syncthreads();
    if (tid == 0) {
        float t = 0.f;
        #pragma unroll
        for (int w = 0; w < 8; ++w) t += red[w];
        g_red[blockIdx.x] = t;
        __threadfence();
        unsigned int v = atomicAdd(&g_ctr, 1u);
        amLast = (v == 31u);
    }
    __syncthreads();
    if (amLast && tid < 32) {
        float v = g_red[tid];
        #pragma unroll
        for (int o = 16; o > 0; o >>= 1)
            v += __shfl_xor_sync(0xffffffffu, v, o);
        if (tid == 0) {
            out[0] = v / (float)M_TOTAL;
            g_ctr = 0u;                     // reset for next graph replay
        }
    }
}

// ---------------------------------------------------------------------------
extern "C" void kernel_launch(void* const* d_in, const int* in_sizes, int n_in,
                              void* d_out, int out_size)
{
    const float* zis = (const float*)d_in[0];
    const float* zjs = (const float*)d_in[1];
    float* out = (float*)d_out;

    norm_kernel<<<N_HALF / 8, 256>>>(zis, zjs);

    cudaFuncSetAttribute(simexp_kernel,
                         cudaFuncAttributeMaxDynamicSharedMemorySize, SMEM_BYTES);
    simexp_kernel<<<dim3(16, NT64), 256, SMEM_BYTES>>>();

    loss_kernel<<<32, 256>>>(out);
}